// round 1
// baseline (speedup 1.0000x reference)
#include <cuda_runtime.h>
#include <math.h>

#define T_TOKENS 32768
#define D_MODEL  1024
#define N_EXP    64
#define TOPK     8
#define TILE_T   64
#define BK       32
#define THREADS  256

__device__ __forceinline__ void ffma2(unsigned long long &acc,
                                      unsigned long long a,
                                      unsigned long long b) {
    asm("fma.rn.f32x2 %0, %1, %2, %0;" : "+l"(acc) : "l"(a), "l"(b));
}

// Fused: fp32 GEMM (logits+noise-std) -> noisy softmax -> mask -> top-8 -> renorm
__global__ void __launch_bounds__(THREADS, 2)
router_topk_kernel(const float* __restrict__ A,      // [T, D]
                   const float* __restrict__ W,      // [D, 2E] = [1024,128]
                   const float* __restrict__ noise,  // [T, E]
                   const int*   __restrict__ mask,   // [T, E]
                   float* __restrict__ out, int out_size)
{
    // smem: GEMM phase: Asd (duplicated-pair A tile) + Ws ; epilogue phase: Cs
    __shared__ __align__(16) char smem[33536];
    float2* Asd = (float2*)smem;                 // [64][33] float2 (pad 33 to kill bank conflicts)
    float*  Ws  = (float*)(smem + 16896);        // [32][128]
    float*  Cs  = (float*)smem;                  // [64][128]

    const int tid = threadIdx.x;
    const int tx  = tid & 15;    // expert-pair group: owns cols {2*tx+32*j, +1}, j=0..3
    const int ty  = tid >> 4;    // token group: owns tokens 4*ty .. 4*ty+3
    const int t0  = blockIdx.x * TILE_T;

    unsigned long long acc[4][4];
#pragma unroll
    for (int i = 0; i < 4; i++)
#pragma unroll
        for (int j = 0; j < 4; j++) acc[i][j] = 0ull;

    for (int kb = 0; kb < D_MODEL; kb += BK) {
        // ---- load A tile [64 x 32], duplicated (a,a) pairs ----
#pragma unroll
        for (int s = tid; s < (TILE_T * BK / 4); s += THREADS) {   // 512 float4 slots
            int row = s >> 3, c4 = s & 7;
            float4 v = *(const float4*)(A + (size_t)(t0 + row) * D_MODEL + kb + c4 * 4);
            float2* dst = Asd + row * 33 + c4 * 4;
            dst[0] = make_float2(v.x, v.x);
            dst[1] = make_float2(v.y, v.y);
            dst[2] = make_float2(v.z, v.z);
            dst[3] = make_float2(v.w, v.w);
        }
        // ---- load W tile [32 x 128] ----
#pragma unroll
        for (int s = tid; s < (BK * 128 / 4); s += THREADS) {      // 1024 float4 slots
            int row = s >> 5, c4 = s & 31;
            *(float4*)(Ws + row * 128 + c4 * 4) =
                *(const float4*)(W + (size_t)(kb + row) * 128 + c4 * 4);
        }
        __syncthreads();

        // ---- inner product: 8 LDS.64 + 16 FFMA2 per k ----
#pragma unroll
        for (int kk = 0; kk < BK; kk++) {
            unsigned long long ap[4];
#pragma unroll
            for (int i = 0; i < 4; i++)
                ap[i] = *(const unsigned long long*)(Asd + (ty * 4 + i) * 33 + kk);
#pragma unroll
            for (int j = 0; j < 4; j++) {
                unsigned long long wp =
                    *(const unsigned long long*)(Ws + kk * 128 + 2 * tx + 32 * j);
#pragma unroll
                for (int i = 0; i < 4; i++) ffma2(acc[i][j], ap[i], wp);
            }
        }
        __syncthreads();
    }

    // ---- spill C tile [64 x 128] to smem for per-token epilogue ----
#pragma unroll
    for (int i = 0; i < 4; i++) {
        int row = ty * 4 + i;
#pragma unroll
        for (int j = 0; j < 4; j++) {
            int c = 2 * tx + 32 * j;
            *(float2*)(Cs + row * 128 + c) = *(float2*)&acc[i][j];
        }
    }
    __syncthreads();

    // ---- epilogue: warp w handles tokens 8w..8w+7; lane owns experts {lane, lane+32} ----
    const int warp = tid >> 5, lane = tid & 31;
    const bool want_idx = (out_size >= 2 * T_TOKENS * TOPK);

    for (int tt = 0; tt < 8; tt++) {
        int t  = warp * 8 + tt;
        int gt = t0 + t;
        const float* crow = Cs + t * 128;

        float lg0 = crow[lane],      lg1 = crow[lane + 32];
        float rn0 = crow[64 + lane], rn1 = crow[96 + lane];
        float ns0 = 1.f / (1.f + expf(-rn0)) + 0.01f;
        float ns1 = 1.f / (1.f + expf(-rn1)) + 0.01f;
        float v0 = fmaf(noise[gt * 64 + lane],      ns0, lg0);
        float v1 = fmaf(noise[gt * 64 + lane + 32], ns1, lg1);

        // softmax over all 64 (mask applied AFTER softmax, as in reference)
        float mx = fmaxf(v0, v1);
#pragma unroll
        for (int o = 16; o; o >>= 1) mx = fmaxf(mx, __shfl_xor_sync(0xffffffffu, mx, o));
        float p0 = expf(v0 - mx), p1 = expf(v1 - mx);
        float s = p0 + p1;
#pragma unroll
        for (int o = 16; o; o >>= 1) s += __shfl_xor_sync(0xffffffffu, s, o);
        float inv = 1.f / s;
        p0 *= inv; p1 *= inv;
        if (mask[gt * 64 + lane] == 0)      p0 = 0.f;
        if (mask[gt * 64 + lane + 32] == 0) p1 = 0.f;

        // top-8 by repeated warp argmax (tie -> lowest index, matches lax.top_k)
        float sel_p = 0.f; int sel_i = 0; float topsum = 0.f;
#pragma unroll
        for (int it = 0; it < TOPK; it++) {
            float cp; int ci;
            if (p1 > p0) { cp = p1; ci = lane + 32; } else { cp = p0; ci = lane; }
#pragma unroll
            for (int o = 16; o; o >>= 1) {
                float op = __shfl_xor_sync(0xffffffffu, cp, o);
                int   oi = __shfl_xor_sync(0xffffffffu, ci, o);
                if (op > cp || (op == cp && oi < ci)) { cp = op; ci = oi; }
            }
            topsum += cp;
            if (lane == it) { sel_p = cp; sel_i = ci; }
            if (ci == lane)           p0 = -1.f;
            else if (ci == lane + 32) p1 = -1.f;
        }
        float rinv = 1.f / (topsum + 1e-6f);
        if (lane < TOPK) {
            out[(size_t)gt * TOPK + lane] = sel_p * rinv;
            if (want_idx)
                out[(size_t)T_TOKENS * TOPK + (size_t)gt * TOPK + lane] = (float)sel_i;
        }
    }
}

extern "C" void kernel_launch(void* const* d_in, const int* in_sizes, int n_in,
                              void* d_out, int out_size)
{
    const float* A     = (const float*)d_in[0];
    const float* W     = (const float*)d_in[1];
    const float* noise = (const float*)d_in[2];
    const int*   mask  = (const int*)d_in[3];
    router_topk_kernel<<<T_TOKENS / TILE_T, THREADS>>>(A, W, noise, mask,
                                                       (float*)d_out, out_size);
}

// round 3
// speedup vs baseline: 1.1087x; 1.1087x over previous
#include <cuda_runtime.h>
#include <math.h>

#define T_TOKENS 32768
#define D_MODEL  1024
#define TOPK     8
#define TILE_T   64
#define BK       16
#define NSTAGE   (D_MODEL / BK)
#define THREADS  256

__device__ __forceinline__ void ffma2(unsigned long long &acc,
                                      unsigned long long a,
                                      unsigned long long b) {
    asm("fma.rn.f32x2 %0, %1, %2, %0;" : "+l"(acc) : "l"(a), "l"(b));
}
__device__ __forceinline__ void cpa16(unsigned int dst, const void* src) {
    asm volatile("cp.async.cg.shared.global [%0], [%1], 16;" :: "r"(dst), "l"(src));
}

// smem plan (bytes):
//   Asd: 2 stages x [64][17] float2 (duplicated (a,a) pairs) @ 0 / 8704   (17408)
//   Ws : 2 stages x [16][128] float                          @ 17408 / 25600 (16384)
//   epilogue reuse: Cs [64][128] float @ 0                   (32768)
__global__ void __launch_bounds__(THREADS, 2)
router_topk_kernel(const float* __restrict__ A,      // [T, D]
                   const float* __restrict__ W,      // [D, 128]
                   const float* __restrict__ noise,  // [T, 64]
                   const int*   __restrict__ mask,   // [T, 64]
                   float* __restrict__ out, int out_size)
{
    __shared__ __align__(16) char smem[33792];
    const int tid = threadIdx.x;
    const int tx  = tid & 15;     // expert-pair group: cols {2*tx+32*j, +1}
    const int ty  = tid >> 4;     // token group: tokens 4*ty .. 4*ty+3
    const int t0  = blockIdx.x * TILE_T;
    const unsigned int smem_u32 = (unsigned int)__cvta_generic_to_shared(smem);

    // A tile staging: thread loads one float4: row = tid>>2 (16 floats/row), c4 = tid&3
    const int a_row = tid >> 2, a_c4 = tid & 3;
    const float4* a_src = (const float4*)(A + (size_t)(t0 + a_row) * D_MODEL + a_c4 * 4);

    // W tile staging via cp.async: 512 x 16B chunks, 2 per thread
    //   chunk q: row = q>>5 (of 16), c = q&31 (32 x 16B per 128-float row)
    auto cp_w = [&](int stage, int kb) {
        unsigned int wBase = smem_u32 + 17408 + stage * 8192;
#pragma unroll
        for (int r = 0; r < 2; r++) {
            int q = tid + r * 256;
            cpa16(wBase + q * 16, W + (size_t)(kb + (q >> 5)) * 128 + (q & 31) * 4);
        }
        asm volatile("cp.async.commit_group;" ::: "memory");
    };
    auto sts_a = [&](int stage, float4 v) {
        float2* dst = (float2*)(smem + stage * 8704) + a_row * 17 + a_c4 * 4;
        dst[0] = make_float2(v.x, v.x);
        dst[1] = make_float2(v.y, v.y);
        dst[2] = make_float2(v.z, v.z);
        dst[3] = make_float2(v.w, v.w);
    };

    unsigned long long acc[4][4];
#pragma unroll
    for (int i = 0; i < 4; i++)
#pragma unroll
        for (int j = 0; j < 4; j++) acc[i][j] = 0ull;

    // ---- prologue: stage 0 ----
    {
        float4 a0 = a_src[0];      // kb = 0
        cp_w(0, 0);
        sts_a(0, a0);
    }

    for (int s = 0; s < NSTAGE; s++) {
        asm volatile("cp.async.wait_group 0;" ::: "memory");
        __syncthreads();           // stage s (A + W) visible; stage s^1 free

        float4 a_next;
        const bool more = (s + 1 < NSTAGE);
        if (more) {
            a_next = a_src[(s + 1) * (BK / 4)];   // LDG in flight during compute
            cp_w((s + 1) & 1, (s + 1) * BK);
        }

        const float2* As = (const float2*)(smem + (s & 1) * 8704);
        const float*  Wm = (const float*)(smem + 17408 + (s & 1) * 8192);

#pragma unroll
        for (int kk = 0; kk < BK; kk++) {
            unsigned long long av[4];
#pragma unroll
            for (int i = 0; i < 4; i++)
                av[i] = *(const unsigned long long*)(As + (ty * 4 + i) * 17 + kk);
#pragma unroll
            for (int j = 0; j < 4; j++) {
                unsigned long long wv =
                    *(const unsigned long long*)(Wm + kk * 128 + 2 * tx + 32 * j);
#pragma unroll
                for (int i = 0; i < 4; i++) ffma2(acc[i][j], av[i], wv);
            }
        }

        if (more) sts_a((s + 1) & 1, a_next);
    }
    __syncthreads();

    // ---- spill C [64][128] to smem ----
    float* Cs = (float*)smem;
#pragma unroll
    for (int i = 0; i < 4; i++) {
        int t = ty * 4 + i;
#pragma unroll
        for (int j = 0; j < 4; j++)
            *(float2*)(Cs + t * 128 + 2 * tx + 32 * j) = *(float2*)&acc[i][j];
    }
    __syncthreads();

    // ---- epilogue: warp w -> tokens 8w..8w+7; lane owns experts {lane, lane+32} ----
    const int warp = tid >> 5, lane = tid & 31;
    const bool want_idx = (out_size >= 2 * T_TOKENS * TOPK);

    for (int tt = 0; tt < 8; tt++) {
        int t  = warp * 8 + tt;
        int gt = t0 + t;
        const float* crow = Cs + t * 128;

        float lg0 = crow[lane],      lg1 = crow[lane + 32];
        float rn0 = crow[64 + lane], rn1 = crow[96 + lane];
        float ns0 = 1.f / (1.f + expf(-rn0)) + 0.01f;
        float ns1 = 1.f / (1.f + expf(-rn1)) + 0.01f;
        float v0 = fmaf(noise[gt * 64 + lane],      ns0, lg0);
        float v1 = fmaf(noise[gt * 64 + lane + 32], ns1, lg1);

        float mx = fmaxf(v0, v1);
#pragma unroll
        for (int o = 16; o; o >>= 1) mx = fmaxf(mx, __shfl_xor_sync(0xffffffffu, mx, o));
        float p0 = expf(v0 - mx), p1 = expf(v1 - mx);
        float ssum = p0 + p1;
#pragma unroll
        for (int o = 16; o; o >>= 1) ssum += __shfl_xor_sync(0xffffffffu, ssum, o);
        float inv = 1.f / ssum;
        p0 *= inv; p1 *= inv;
        if (mask[gt * 64 + lane] == 0)      p0 = 0.f;
        if (mask[gt * 64 + lane + 32] == 0) p1 = 0.f;

        float sel_p = 0.f; int sel_i = 0; float topsum = 0.f;
#pragma unroll
        for (int it = 0; it < TOPK; it++) {
            float cp; int ci;
            if (p1 > p0) { cp = p1; ci = lane + 32; } else { cp = p0; ci = lane; }
#pragma unroll
            for (int o = 16; o; o >>= 1) {
                float op = __shfl_xor_sync(0xffffffffu, cp, o);
                int   oi = __shfl_xor_sync(0xffffffffu, ci, o);
                if (op > cp || (op == cp && oi < ci)) { cp = op; ci = oi; }
            }
            topsum += cp;
            if (lane == it) { sel_p = cp; sel_i = ci; }
            if (ci == lane)           p0 = -1.f;
            else if (ci == lane + 32) p1 = -1.f;
        }
        float rinv = 1.f / (topsum + 1e-6f);
        if (lane < TOPK) {
            out[(size_t)gt * TOPK + lane] = sel_p * rinv;
            if (want_idx)
                out[(size_t)T_TOKENS * TOPK + (size_t)gt * TOPK + lane] = (float)sel_i;
        }
    }
}

extern "C" void kernel_launch(void* const* d_in, const int* in_sizes, int n_in,
                              void* d_out, int out_size)
{
    const float* A     = (const float*)d_in[0];
    const float* W     = (const float*)d_in[1];
    const float* noise = (const float*)d_in[2];
    const int*   mask  = (const int*)d_in[3];
    router_topk_kernel<<<T_TOKENS / TILE_T, THREADS>>>(A, W, noise, mask,
                                                       (float*)d_out, out_size);
}

// round 4
// speedup vs baseline: 1.1164x; 1.0070x over previous
#include <cuda_runtime.h>
#include <math.h>

#define T_TOKENS 32768
#define D_MODEL  1024
#define TOPK     8
#define TILE_T   64
#define BK       16
#define NSTAGE   (D_MODEL / BK)
#define THREADS  256

// smem plan (bytes):
//   Asd: 2 stages x [64 tok][18 float2] duplicated (a,a)  @ 0 / 9216    (18432)
//   Ws : 2 stages x [16 k][128 e] float                    @ 18432 / 26624 (16384)
//   epilogue reuse: Cs [64][128] float @ 0                 (32768)
#define A_STRIDE 18
#define A_STAGE  9216
#define W_OFF    18432
#define W_STAGE  8192
#define SMEM_SZ  34816

__device__ __forceinline__ void ffma2(unsigned long long &acc,
                                      unsigned long long a,
                                      unsigned long long b) {
    asm("fma.rn.f32x2 %0, %1, %2, %0;" : "+l"(acc) : "l"(a), "l"(b));
}
__device__ __forceinline__ void cpa16(unsigned int dst, const void* src) {
    asm volatile("cp.async.cg.shared.global [%0], [%1], 16;" :: "r"(dst), "l"(src));
}

__global__ void __launch_bounds__(THREADS, 2)
router_topk_kernel(const float* __restrict__ A,      // [T, D]
                   const float* __restrict__ W,      // [D, 128]
                   const float* __restrict__ noise,  // [T, 64]
                   const int*   __restrict__ mask,   // [T, 64]
                   float* __restrict__ out, int out_size)
{
    __shared__ __align__(16) char smem[SMEM_SZ];
    const int tid  = threadIdx.x;
    const int warp = tid >> 5, lane = tid & 31;
    const int tx16 = lane & 15, hh = lane >> 4;      // expert base e0 = 4*tx16 + 64*hh
    const int wcol = 4 * tx16 + 64 * hh;             // float offset within W row
    const int tok0 = warp * 8;                       // warp's first token (local)
    const int t0   = blockIdx.x * TILE_T;
    const unsigned int smem_u32 = (unsigned int)__cvta_generic_to_shared(smem);

    // A staging: thread loads one float4/stage: row = tid>>2 (16 floats/row), c4 = tid&3
    const int a_row = tid >> 2, a_c4 = tid & 3;
    const float4* a_src = (const float4*)(A + (size_t)(t0 + a_row) * D_MODEL + a_c4 * 4);

    auto cp_w = [&](int stage, int kb) {             // 512 x 16B chunks, 2/thread
        unsigned int wBase = smem_u32 + W_OFF + stage * W_STAGE;
#pragma unroll
        for (int r = 0; r < 2; r++) {
            int q = tid + r * 256;
            cpa16(wBase + q * 16, W + (size_t)(kb + (q >> 5)) * 128 + (q & 31) * 4);
        }
        asm volatile("cp.async.commit_group;" ::: "memory");
    };
    auto sts_a = [&](int stage, float4 v) {          // duplicated (a,a) pairs
        float2* dst = (float2*)(smem + stage * A_STAGE) + a_row * A_STRIDE + a_c4 * 4;
        dst[0] = make_float2(v.x, v.x);
        dst[1] = make_float2(v.y, v.y);
        dst[2] = make_float2(v.z, v.z);
        dst[3] = make_float2(v.w, v.w);
    };

    unsigned long long acc[8][2];                    // 8 tokens x 2 expert-pairs
#pragma unroll
    for (int i = 0; i < 8; i++) { acc[i][0] = 0ull; acc[i][1] = 0ull; }

    { float4 a0 = a_src[0]; cp_w(0, 0); sts_a(0, a0); }

    for (int s = 0; s < NSTAGE; s++) {
        asm volatile("cp.async.wait_group 0;" ::: "memory");
        __syncthreads();

        float4 a_next;
        const bool more = (s + 1 < NSTAGE);
        if (more) {
            a_next = a_src[(s + 1) * (BK / 4)];
            cp_w((s + 1) & 1, (s + 1) * BK);
        }

        const float2* As = (const float2*)(smem + (s & 1) * A_STAGE);
        const float*  Wm = (const float*)(smem + W_OFF + (s & 1) * W_STAGE);

#pragma unroll
        for (int kp = 0; kp < BK / 2; kp++) {        // 2 k per iteration
            ulonglong2 w0 = *(const ulonglong2*)(Wm + (2 * kp)     * 128 + wcol);
            ulonglong2 w1 = *(const ulonglong2*)(Wm + (2 * kp + 1) * 128 + wcol);
#pragma unroll
            for (int i = 0; i < 8; i++) {
                ulonglong2 av = *(const ulonglong2*)
                                (As + (tok0 + i) * A_STRIDE + 2 * kp);
                ffma2(acc[i][0], av.x, w0.x);        // k
                ffma2(acc[i][1], av.x, w0.y);
                ffma2(acc[i][0], av.y, w1.x);        // k+1
                ffma2(acc[i][1], av.y, w1.y);
            }
        }

        if (more) sts_a((s + 1) & 1, a_next);
    }
    __syncthreads();

    // ---- spill C [64][128] ----
    float* Cs = (float*)smem;
#pragma unroll
    for (int i = 0; i < 8; i++) {
        int t = tok0 + i;
        *(float2*)(Cs + t * 128 + wcol)     = *(float2*)&acc[i][0];
        *(float2*)(Cs + t * 128 + wcol + 2) = *(float2*)&acc[i][1];
    }
    __syncthreads();

    // ---- epilogue: warp w -> tokens 8w..8w+7; lane owns experts {lane, lane+32} ----
    const bool want_idx = (out_size >= 2 * T_TOKENS * TOPK);

    for (int tt = 0; tt < 8; tt++) {
        int t  = tok0 + tt;
        int gt = t0 + t;
        const float* crow = Cs + t * 128;

        float lg0 = crow[lane],      lg1 = crow[lane + 32];
        float rn0 = crow[64 + lane], rn1 = crow[96 + lane];
        float ns0 = 1.f / (1.f + expf(-rn0)) + 0.01f;
        float ns1 = 1.f / (1.f + expf(-rn1)) + 0.01f;
        float v0 = fmaf(noise[gt * 64 + lane],      ns0, lg0);
        float v1 = fmaf(noise[gt * 64 + lane + 32], ns1, lg1);

        float mx = fmaxf(v0, v1);
#pragma unroll
        for (int o = 16; o; o >>= 1) mx = fmaxf(mx, __shfl_xor_sync(0xffffffffu, mx, o));
        float p0 = expf(v0 - mx), p1 = expf(v1 - mx);
        float ssum = p0 + p1;
#pragma unroll
        for (int o = 16; o; o >>= 1) ssum += __shfl_xor_sync(0xffffffffu, ssum, o);
        float inv = 1.f / ssum;
        p0 *= inv; p1 *= inv;
        if (mask[gt * 64 + lane] == 0)      p0 = 0.f;
        if (mask[gt * 64 + lane + 32] == 0) p1 = 0.f;

        float sel_p = 0.f; int sel_i = 0; float topsum = 0.f;
#pragma unroll
        for (int it = 0; it < TOPK; it++) {
            float cp; int ci;
            if (p1 > p0) { cp = p1; ci = lane + 32; } else { cp = p0; ci = lane; }
#pragma unroll
            for (int o = 16; o; o >>= 1) {
                float op = __shfl_xor_sync(0xffffffffu, cp, o);
                int   oi = __shfl_xor_sync(0xffffffffu, ci, o);
                if (op > cp || (op == cp && oi < ci)) { cp = op; ci = oi; }
            }
            topsum += cp;
            if (lane == it) { sel_p = cp; sel_i = ci; }
            if (ci == lane)           p0 = -1.f;
            else if (ci == lane + 32) p1 = -1.f;
        }
        float rinv = 1.f / (topsum + 1e-6f);
        if (lane < TOPK) {
            out[(size_t)gt * TOPK + lane] = sel_p * rinv;
            if (want_idx)
                out[(size_t)T_TOKENS * TOPK + (size_t)gt * TOPK + lane] = (float)sel_i;
        }
    }
}

extern "C" void kernel_launch(void* const* d_in, const int* in_sizes, int n_in,
                              void* d_out, int out_size)
{
    const float* A     = (const float*)d_in[0];
    const float* W     = (const float*)d_in[1];
    const float* noise = (const float*)d_in[2];
    const int*   mask  = (const int*)d_in[3];
    router_topk_kernel<<<T_TOKENS / TILE_T, THREADS>>>(A, W, noise, mask,
                                                       (float*)d_out, out_size);
}

// round 5
// speedup vs baseline: 1.4139x; 1.2665x over previous
#include <cuda_runtime.h>
#include <math.h>

#define T_TOKENS 32768
#define D_MODEL  1024
#define TOPK     8
#define TILE_T   64
#define BK       32
#define NSTAGE   (D_MODEL / BK)
#define THREADS  256

// dynamic smem plan (bytes):
//   As : 2 stages x [32 k][68 floats] transposed A   @ 0      (2 x 8704 = 17408)
//   Ws : 2 stages x [32 k][128 e] float              @ 17408  (2 x 16384 = 32768)
//   epilogue reuse: Cs [64][128] float               @ 0      (32768)
#define A_STRIDE 68
#define A_STAGE  8704
#define W_OFF    17408
#define W_STAGE  16384
#define SMEM_SZ  50176

__device__ __forceinline__ void ffma2(unsigned long long &acc,
                                      unsigned long long a,
                                      unsigned long long b) {
    asm("fma.rn.f32x2 %0, %1, %2, %0;" : "+l"(acc) : "l"(a), "l"(b));
}
__device__ __forceinline__ unsigned long long dup2(float w) {
    unsigned long long r;
    asm("mov.b64 %0, {%1, %1};" : "=l"(r) : "f"(w));
    return r;
}
__device__ __forceinline__ void cpa16(unsigned int dst, const void* src) {
    asm volatile("cp.async.cg.shared.global [%0], [%1], 16;" :: "r"(dst), "l"(src));
}

extern __shared__ char smem[];

__global__ void __launch_bounds__(THREADS, 3)
router_topk_kernel(const float* __restrict__ A,      // [T, D]
                   const float* __restrict__ W,      // [D, 128]
                   const float* __restrict__ noise,  // [T, 64]
                   const int*   __restrict__ mask,   // [T, 64]
                   float* __restrict__ out, int out_size)
{
    const int tid  = threadIdx.x;
    const int warp = tid >> 5, lane = tid & 31;
    const int tx16 = lane & 15, hh = lane >> 4;
    const int wcol = 4 * tx16 + 64 * hh;         // 4 consecutive experts per lane
    const int tok0 = warp * 8;                   // warp's 8 tokens (local)
    const int t0   = blockIdx.x * TILE_T;
    const unsigned int smem_u32 = (unsigned int)__cvta_generic_to_shared(smem);

    // A staging: thread owns token a_tok, k-groups a_c and a_c+4 (2 float4 per stage)
    const int a_tok = tid >> 2, a_c = tid & 3;
    const float* a_base = A + (size_t)(t0 + a_tok) * D_MODEL;

    auto cp_w = [&](int stage, int kb) {         // 1024 x 16B chunks, 4/thread
        unsigned int wBase = smem_u32 + W_OFF + stage * W_STAGE;
#pragma unroll
        for (int r = 0; r < 4; r++) {
            int q = tid + r * 256;
            cpa16(wBase + q * 16, W + (size_t)(kb + (q >> 5)) * 128 + (q & 31) * 4);
        }
        asm volatile("cp.async.commit_group;" ::: "memory");
    };
    auto sts_a = [&](int stage, float4 v0, float4 v1) {   // transposed scatter
        float* As = (float*)(smem + stage * A_STAGE);
#pragma unroll
        for (int j = 0; j < 4; j++) {
            As[(4 * a_c + j) * A_STRIDE + a_tok]       = ((const float*)&v0)[j];
            As[(4 * (a_c + 4) + j) * A_STRIDE + a_tok] = ((const float*)&v1)[j];
        }
    };

    unsigned long long acc[4][4];                // [token-pair][expert]
#pragma unroll
    for (int p = 0; p < 4; p++)
#pragma unroll
        for (int j = 0; j < 4; j++) acc[p][j] = 0ull;

    {   // prologue: stage 0
        float4 v0 = *(const float4*)(a_base + a_c * 4);
        float4 v1 = *(const float4*)(a_base + (a_c + 4) * 4);
        cp_w(0, 0);
        sts_a(0, v0, v1);
    }

    for (int s = 0; s < NSTAGE; s++) {
        asm volatile("cp.async.wait_group 0;" ::: "memory");
        __syncthreads();

        float4 v0, v1;
        const bool more = (s + 1 < NSTAGE);
        if (more) {
            const float* ab = a_base + (s + 1) * BK;
            v0 = *(const float4*)(ab + a_c * 4);
            v1 = *(const float4*)(ab + (a_c + 4) * 4);
            cp_w((s + 1) & 1, (s + 1) * BK);
        }

        const float* As = (const float*)(smem + (s & 1) * A_STAGE);
        const float* Wm = (const float*)(smem + W_OFF + (s & 1) * W_STAGE);

#pragma unroll
        for (int kk = 0; kk < BK; kk++) {
            ulonglong2 avA = *(const ulonglong2*)(As + kk * A_STRIDE + tok0);      // tok 0-3
            ulonglong2 avB = *(const ulonglong2*)(As + kk * A_STRIDE + tok0 + 4);  // tok 4-7
            float4 w4 = *(const float4*)(Wm + kk * 128 + wcol);
            unsigned long long wd0 = dup2(w4.x), wd1 = dup2(w4.y),
                               wd2 = dup2(w4.z), wd3 = dup2(w4.w);
            ffma2(acc[0][0], avA.x, wd0); ffma2(acc[0][1], avA.x, wd1);
            ffma2(acc[0][2], avA.x, wd2); ffma2(acc[0][3], avA.x, wd3);
            ffma2(acc[1][0], avA.y, wd0); ffma2(acc[1][1], avA.y, wd1);
            ffma2(acc[1][2], avA.y, wd2); ffma2(acc[1][3], avA.y, wd3);
            ffma2(acc[2][0], avB.x, wd0); ffma2(acc[2][1], avB.x, wd1);
            ffma2(acc[2][2], avB.x, wd2); ffma2(acc[2][3], avB.x, wd3);
            ffma2(acc[3][0], avB.y, wd0); ffma2(acc[3][1], avB.y, wd1);
            ffma2(acc[3][2], avB.y, wd2); ffma2(acc[3][3], avB.y, wd3);
        }

        if (more) sts_a((s + 1) & 1, v0, v1);
    }
    __syncthreads();

    // ---- spill C [64][128] : acc[p][j] = (tok0+2p, tok0+2p+1) x expert wcol+j ----
    float* Cs = (float*)smem;
#pragma unroll
    for (int p = 0; p < 4; p++)
#pragma unroll
        for (int j = 0; j < 4; j++) {
            float2 f = *(float2*)&acc[p][j];
            Cs[(tok0 + 2 * p)     * 128 + wcol + j] = f.x;
            Cs[(tok0 + 2 * p + 1) * 128 + wcol + j] = f.y;
        }
    __syncthreads();

    // ---- epilogue: warp -> its 8 tokens; lane owns experts {lane, lane+32} ----
    const bool want_idx = (out_size >= 2 * T_TOKENS * TOPK);

    for (int tt = 0; tt < 8; tt++) {
        int t  = tok0 + tt;
        int gt = t0 + t;
        const float* crow = Cs + t * 128;

        float lg0 = crow[lane],      lg1 = crow[lane + 32];
        float rn0 = crow[64 + lane], rn1 = crow[96 + lane];
        float ns0 = 1.f / (1.f + expf(-rn0)) + 0.01f;
        float ns1 = 1.f / (1.f + expf(-rn1)) + 0.01f;
        float v0 = fmaf(noise[gt * 64 + lane],      ns0, lg0);
        float v1 = fmaf(noise[gt * 64 + lane + 32], ns1, lg1);

        float mx = fmaxf(v0, v1);
#pragma unroll
        for (int o = 16; o; o >>= 1) mx = fmaxf(mx, __shfl_xor_sync(0xffffffffu, mx, o));
        float p0 = expf(v0 - mx), p1 = expf(v1 - mx);
        float ssum = p0 + p1;
#pragma unroll
        for (int o = 16; o; o >>= 1) ssum += __shfl_xor_sync(0xffffffffu, ssum, o);
        float inv = 1.f / ssum;
        p0 *= inv; p1 *= inv;
        if (mask[gt * 64 + lane] == 0)      p0 = 0.f;
        if (mask[gt * 64 + lane + 32] == 0) p1 = 0.f;

        float sel_p = 0.f; int sel_i = 0; float topsum = 0.f;
#pragma unroll
        for (int it = 0; it < TOPK; it++) {
            float cp; int ci;
            if (p1 > p0) { cp = p1; ci = lane + 32; } else { cp = p0; ci = lane; }
#pragma unroll
            for (int o = 16; o; o >>= 1) {
                float op = __shfl_xor_sync(0xffffffffu, cp, o);
                int   oi = __shfl_xor_sync(0xffffffffu, ci, o);
                if (op > cp || (op == cp && oi < ci)) { cp = op; ci = oi; }
            }
            topsum += cp;
            if (lane == it) { sel_p = cp; sel_i = ci; }
            if (ci == lane)           p0 = -1.f;
            else if (ci == lane + 32) p1 = -1.f;
        }
        float rinv = 1.f / (topsum + 1e-6f);
        if (lane < TOPK) {
            out[(size_t)gt * TOPK + lane] = sel_p * rinv;
            if (want_idx)
                out[(size_t)T_TOKENS * TOPK + (size_t)gt * TOPK + lane] = (float)sel_i;
        }
    }
}

extern "C" void kernel_launch(void* const* d_in, const int* in_sizes, int n_in,
                              void* d_out, int out_size)
{
    const float* A     = (const float*)d_in[0];
    const float* W     = (const float*)d_in[1];
    const float* noise = (const float*)d_in[2];
    const int*   mask  = (const int*)d_in[3];

    cudaFuncSetAttribute(router_topk_kernel,
                         cudaFuncAttributeMaxDynamicSharedMemorySize, SMEM_SZ);
    router_topk_kernel<<<T_TOKENS / TILE_T, THREADS, SMEM_SZ>>>(A, W, noise, mask,
                                                                (float*)d_out, out_size);
}